// round 15
// baseline (speedup 1.0000x reference)
#include <cuda_runtime.h>
#include <math.h>
#include <stdint.h>

#define NB_   7
#define S_    16
#define D_    128
#define B_    32
#define T_    2048
#define KMAX_ 31

// Scratch (device globals; no allocations allowed)
__device__ float g_p[(size_t)B_ * T_ * NB_ * 4 * S_];    // cat layout  [b][t][nb][4S]

// Fragment-major packed tf32 weights (permuted in k_prep)
#define NWC (NB_ * KMAX_ * S_ * D_)      // 444416
#define NW1 (NB_ * D_ * 2 * D_)          // 229376
#define NW2 (NB_ * 2 * D_ * D_)          // 229376
#define NWP (NB_ * D_ * 64)              // 57344
#define NWM (448 * 128)                  // 57344
__device__ float g_wc[NWC];
__device__ float g_w1[NW1];
__device__ float g_w2[NW2];
__device__ float g_wp[NWP];
__device__ float g_wm[NWM];

__device__ __forceinline__ float gelu_exact(float v) {
    return 0.5f * v * (1.0f + erff(v * 0.70710678118654752440f));
}

__device__ __forceinline__ uint32_t f2tf(float f) {
    uint32_t r;
    asm("cvt.rna.tf32.f32 %0, %1;" : "=r"(r) : "f"(f));
    return r;
}
__device__ __forceinline__ float f2tf_f(float f) { return __uint_as_float(f2tf(f)); }

__device__ __forceinline__ void mma_tf32(float c[4],
    uint32_t a0, uint32_t a1, uint32_t a2, uint32_t a3,
    uint32_t b0, uint32_t b1)
{
    asm volatile(
        "mma.sync.aligned.m16n8k8.row.col.f32.tf32.tf32.f32 "
        "{%0,%1,%2,%3},{%4,%5,%6,%7},{%8,%9},{%0,%1,%2,%3};"
        : "+f"(c[0]), "+f"(c[1]), "+f"(c[2]), "+f"(c[3])
        : "r"(a0), "r"(a1), "r"(a2), "r"(a3), "r"(b0), "r"(b1));
}

// ---------------------------------------------------------------------------
// Kernel 0: tf32-round + permute all GEMM weights into fragment-major order.
// (identical to R12)
// ---------------------------------------------------------------------------
__global__ __launch_bounds__(256) void k_prep(
    const float* __restrict__ cw, const float* __restrict__ w1,
    const float* __restrict__ w2, const float* __restrict__ pw,
    const float* __restrict__ mw1)
{
    const int stride = gridDim.x * blockDim.x;
    const int i0 = blockIdx.x * blockDim.x + threadIdx.x;

    for (int i = i0; i < NW1; i += stride) {
        int pair = i & 1, nt = (i >> 1) & 3, lane = (i >> 3) & 31;
        int w = (i >> 8) & 7, kb = (i >> 11) & 15, band = i >> 15;
        int k = kb * 8 + (lane & 3) + pair * 4;
        int col = w * 32 + nt * 8 + (lane >> 2);
        g_w1[i] = f2tf_f(w1[((size_t)band * 128 + k) * 256 + col]);
    }
    for (int i = i0; i < NW2; i += stride) {
        int pair = i & 1, nt = (i >> 1) & 1, lane = (i >> 2) & 31;
        int w = (i >> 7) & 7, kb = (i >> 10) & 31, band = i >> 15;
        int k = kb * 8 + (lane & 3) + pair * 4;
        int col = w * 16 + nt * 8 + (lane >> 2);
        g_w2[i] = f2tf_f(w2[((size_t)band * 256 + k) * 128 + col]);
    }
    for (int i = i0; i < NWP; i += stride) {
        int pair = i & 1, lane = (i >> 1) & 31;
        int w = (i >> 6) & 7, kb = (i >> 9) & 15, band = i >> 13;
        int k = kb * 8 + (lane & 3) + pair * 4;
        int col = w * 8 + (lane >> 2);
        g_wp[i] = f2tf_f(pw[((size_t)band * 128 + k) * 64 + col]);
    }
    for (int i = i0; i < NWC; i += stride) {
        int sub = i & 1023;
        int pair = sub & 1, nt = (sub >> 1) & 1, lane = (sub >> 2) & 31, w = sub >> 7;
        int rest = i >> 10;
        int c8 = rest & 1; rest >>= 1;
        int k = rest % 31, band = rest / 31;
        int s = c8 * 8 + (lane & 3) + pair * 4;
        int col = w * 16 + nt * 8 + (lane >> 2);
        g_wc[i] = f2tf_f(cw[(((size_t)band * 31 + k) * 16 + s) * 128 + col]);
    }
    for (int i = i0; i < NWM; i += stride) {
        int pair = i & 1, nt = (i >> 1) & 1, lane = (i >> 2) & 31;
        int w = (i >> 7) & 7, kb = i >> 10;
        int k = kb * 8 + (lane & 3) + pair * 4;
        int col = w * 16 + nt * 8 + (lane >> 2);
        g_wm[i] = f2tf_f(mw1[(size_t)k * 128 + col]);
    }
}

// ---------------------------------------------------------------------------
// Kernel 1 (FUSED, templated on conv kernel size KB; one launch per band):
// conv -> LN1 -> LN2 -> GEMM1(gelu) -> GEMM2(+h) -> proj
// grid (T/32, B), block 256.
// Column micro-permutation c -> (c&~7)|((c&3)<<1)|((c>>2)&1) on xs/zs/us
// makes A-fragment pairs adjacent => LDS.64 loads, conflict-free (stride≡4 mod 32).
// smem: pool[8320] (xs 62*36=2232 | us 32*260), hs[32*132], zs[32*132]
// ---------------------------------------------------------------------------
#define XSTR 36
#define HP   132
#define ZP   132
#define UP   260

template<int KB>
__global__ __launch_bounds__(256) void k_fused(
    const float* __restrict__ x,
    const float* __restrict__ conv_b,
    const float* __restrict__ dec_g, const float* __restrict__ dec_b,
    const float* __restrict__ n2_g, const float* __restrict__ n2_b,
    const float* __restrict__ fb1, const float* __restrict__ fb2,
    const float* __restrict__ pb, int band)
{
    extern __shared__ float sm[];
    float* pool = sm;               // xs (62*36) then us (32*260=8320)
    float* xs = pool;
    float* us = pool;
    float* hs = sm + 8320;          // 32*132
    float* zs = sm + 12544;         // 32*132

    const int b = blockIdx.y;
    const int t0 = blockIdx.x * 32;
    const int tid = threadIdx.x;
    const int warp = tid >> 5, lane = tid & 31;
    const int grp = lane >> 2, tig = lane & 3;
    // packed offsets for epilogue scalar stores: cols (X+tig*2, X+tig*2+1)
    const int off0 = ((tig & 1) << 2) | (tig >> 1);   // packed pos of tig*2
    // lane's packed column position for LN-style writes at (lane + 32c)
    const int lanePk = (lane & ~7) | ((lane & 3) << 1) | ((lane >> 2) & 1);

    // ---- stage x window rows [t0-15, t0+46], tf32-rounded, packed s ----
    const float* xb = x + (size_t)b * T_ * S_;
    for (int i = tid; i < 62 * S_; i += 256) {
        int row = i >> 4, s = i & 15;
        int gt = t0 + row - (KMAX_ / 2);
        float v = (gt >= 0 && gt < T_) ? xb[gt * S_ + s] : 0.0f;
        int sp = (s & 8) | ((s & 3) << 1) | ((s >> 2) & 1);
        xs[row * XSTR + sp] = f2tf_f(v);
    }
    __syncthreads();

    // ---- conv as mma, FULLY UNROLLED taps, LDS.64 A-frags ----
    {
        float acc[2][2][4];
#pragma unroll
        for (int mt = 0; mt < 2; ++mt)
#pragma unroll
            for (int nt = 0; nt < 2; ++nt)
#pragma unroll
                for (int c = 0; c < 4; ++c) acc[mt][nt][c] = 0.0f;

        constexpr int off = (KMAX_ - KB) >> 1;
        const float* xrow = xs + grp * XSTR + tig * 2;
        const float* wcb = g_wc + (((size_t)band * 31 * 2) * 8 + warp) * 32 * 4 + (size_t)lane * 4;

#pragma unroll
        for (int k = off; k < off + KB; ++k) {
#pragma unroll
            for (int c8 = 0; c8 < 2; ++c8) {
                float2 xa[2][2];
#pragma unroll
                for (int mt = 0; mt < 2; ++mt) {
                    const float* xr = xrow + (mt * 16 + k) * XSTR + c8 * 8;
                    xa[mt][0] = *(const float2*)xr;
                    xa[mt][1] = *(const float2*)(xr + 8 * XSTR);
                }
                const float4 wv = __ldg((const float4*)(wcb + (size_t)(k * 2 + c8) * (8 * 32 * 4)));
#pragma unroll
                for (int nt = 0; nt < 2; ++nt) {
                    uint32_t bf0 = __float_as_uint(nt ? wv.z : wv.x);
                    uint32_t bf1 = __float_as_uint(nt ? wv.w : wv.y);
#pragma unroll
                    for (int mt = 0; mt < 2; ++mt)
                        mma_tf32(acc[mt][nt],
                                 __float_as_uint(xa[mt][0].x), __float_as_uint(xa[mt][1].x),
                                 __float_as_uint(xa[mt][0].y), __float_as_uint(xa[mt][1].y),
                                 bf0, bf1);
                }
            }
        }

        // bias -> hs (row-major, pre-LN conv output)
#pragma unroll
        for (int nt = 0; nt < 2; ++nt) {
            int col0 = warp * 16 + nt * 8 + tig * 2;
            float bb0 = conv_b[band * D_ + col0];
            float bb1 = conv_b[band * D_ + col0 + 1];
#pragma unroll
            for (int mt = 0; mt < 2; ++mt) {
                int r0 = mt * 16 + grp;
                hs[r0 * HP + col0]           = acc[mt][nt][0] + bb0;
                hs[r0 * HP + col0 + 1]       = acc[mt][nt][1] + bb1;
                hs[(r0 + 8) * HP + col0]     = acc[mt][nt][2] + bb0;
                hs[(r0 + 8) * HP + col0 + 1] = acc[mt][nt][3] + bb1;
            }
        }
    }
    __syncthreads();   // hs complete; xs dead from here (pool becomes us)

    // ---- combined LN1 + LN2: hs := h (row-major), zs := tf32(z) (packed) ----
    {
        float g1v[4], b1v[4], g2v[4], b2v[4];
#pragma unroll
        for (int c = 0; c < 4; ++c) {
            g1v[c] = dec_g[band * D_ + lane + 32 * c];
            b1v[c] = dec_b[band * D_ + lane + 32 * c];
            g2v[c] = n2_g[band * D_ + lane + 32 * c];
            b2v[c] = n2_b[band * D_ + lane + 32 * c];
        }
        for (int i = 0; i < 4; ++i) {
            int tt = warp * 4 + i;
            float v[4]; float s = 0.0f;
#pragma unroll
            for (int c = 0; c < 4; ++c) { v[c] = hs[tt * HP + lane + 32 * c]; s += v[c]; }
#pragma unroll
            for (int o = 16; o; o >>= 1) s += __shfl_xor_sync(0xffffffffu, s, o);
            float mean = s * (1.0f / 128.0f);
            float q = 0.0f;
#pragma unroll
            for (int c = 0; c < 4; ++c) { float d0 = v[c] - mean; q = fmaf(d0, d0, q); }
#pragma unroll
            for (int o = 16; o; o >>= 1) q += __shfl_xor_sync(0xffffffffu, q, o);
            float rstd = rsqrtf(q * (1.0f / 128.0f) + 1e-5f);

            float hv[4]; float s2 = 0.0f;
#pragma unroll
            for (int c = 0; c < 4; ++c) {
                hv[c] = (v[c] - mean) * rstd * g1v[c] + b1v[c];
                hs[tt * HP + lane + 32 * c] = hv[c];
                s2 += hv[c];
            }
#pragma unroll
            for (int o = 16; o; o >>= 1) s2 += __shfl_xor_sync(0xffffffffu, s2, o);
            float mean2 = s2 * (1.0f / 128.0f);
            float q2 = 0.0f;
#pragma unroll
            for (int c = 0; c < 4; ++c) { float d0 = hv[c] - mean2; q2 = fmaf(d0, d0, q2); }
#pragma unroll
            for (int o = 16; o; o >>= 1) q2 += __shfl_xor_sync(0xffffffffu, q2, o);
            float rstd2 = rsqrtf(q2 * (1.0f / 128.0f) + 1e-5f);
#pragma unroll
            for (int c = 0; c < 4; ++c)
                zs[tt * ZP + lanePk + 32 * c] = f2tf_f((hv[c] - mean2) * rstd2 * g2v[c] + b2v[c]);
        }
    }
    __syncthreads();

    // ---- GEMM1: u = gelu(z @ W1 + b1). Full unroll, LDS.64 A-frags ----
    {
        float acc[2][4][4];
#pragma unroll
        for (int mt = 0; mt < 2; ++mt)
#pragma unroll
            for (int nt = 0; nt < 4; ++nt)
#pragma unroll
                for (int c = 0; c < 4; ++c) acc[mt][nt][c] = 0.0f;

        const float* wbase = g_w1 + ((((size_t)band * 16) * 8 + warp) * 32 + lane) * 8;
        const float* z0 = zs + grp * ZP + tig * 2;
#pragma unroll
        for (int kb = 0; kb < 16; ++kb) {
            const int k0 = kb * 8;
            float2 za[2][2];
#pragma unroll
            for (int mt = 0; mt < 2; ++mt) {
                const float* zm = z0 + mt * 16 * ZP + k0;
                za[mt][0] = *(const float2*)zm;
                za[mt][1] = *(const float2*)(zm + 8 * ZP);
            }
            const float4 w0 = __ldg((const float4*)(wbase + (size_t)kb * 2048));
            const float4 w1v = __ldg((const float4*)(wbase + (size_t)kb * 2048 + 4));
            const float wv[8] = {w0.x, w0.y, w0.z, w0.w, w1v.x, w1v.y, w1v.z, w1v.w};
#pragma unroll
            for (int nt = 0; nt < 4; ++nt) {
                uint32_t bf0 = __float_as_uint(wv[nt * 2]);
                uint32_t bf1 = __float_as_uint(wv[nt * 2 + 1]);
#pragma unroll
                for (int mt = 0; mt < 2; ++mt)
                    mma_tf32(acc[mt][nt],
                             __float_as_uint(za[mt][0].x), __float_as_uint(za[mt][1].x),
                             __float_as_uint(za[mt][0].y), __float_as_uint(za[mt][1].y),
                             bf0, bf1);
            }
        }
#pragma unroll
        for (int nt = 0; nt < 4; ++nt) {
            int colb = warp * 32 + nt * 8;
            int col0 = colb + tig * 2;
            float bb0 = fb1[band * 256 + col0];
            float bb1 = fb1[band * 256 + col0 + 1];
#pragma unroll
            for (int mt = 0; mt < 2; ++mt) {
                int r0 = mt * 16 + grp;
                us[r0 * UP + colb + off0]           = f2tf_f(gelu_exact(acc[mt][nt][0] + bb0));
                us[r0 * UP + colb + off0 + 2]       = f2tf_f(gelu_exact(acc[mt][nt][1] + bb1));
                us[(r0 + 8) * UP + colb + off0]     = f2tf_f(gelu_exact(acc[mt][nt][2] + bb0));
                us[(r0 + 8) * UP + colb + off0 + 2] = f2tf_f(gelu_exact(acc[mt][nt][3] + bb1));
            }
        }
    }
    __syncthreads();

    // ---- GEMM2: band_out = h + u @ W2 + b2 -> zs (packed). Full unroll ----
    {
        float acc[2][2][4];
#pragma unroll
        for (int mt = 0; mt < 2; ++mt)
#pragma unroll
            for (int nt = 0; nt < 2; ++nt)
#pragma unroll
                for (int c = 0; c < 4; ++c) acc[mt][nt][c] = 0.0f;

        const float* wbase = g_w2 + ((((size_t)band * 32) * 8 + warp) * 32 + lane) * 4;
        const float* u0 = us + grp * UP + tig * 2;
#pragma unroll
        for (int kb = 0; kb < 32; ++kb) {
            const int k0 = kb * 8;
            float2 ua[2][2];
#pragma unroll
            for (int mt = 0; mt < 2; ++mt) {
                const float* um = u0 + mt * 16 * UP + k0;
                ua[mt][0] = *(const float2*)um;
                ua[mt][1] = *(const float2*)(um + 8 * UP);
            }
            const float4 wv = __ldg((const float4*)(wbase + (size_t)kb * 1024));
#pragma unroll
            for (int nt = 0; nt < 2; ++nt) {
                uint32_t bf0 = __float_as_uint(nt ? wv.z : wv.x);
                uint32_t bf1 = __float_as_uint(nt ? wv.w : wv.y);
#pragma unroll
                for (int mt = 0; mt < 2; ++mt)
                    mma_tf32(acc[mt][nt],
                             __float_as_uint(ua[mt][0].x), __float_as_uint(ua[mt][1].x),
                             __float_as_uint(ua[mt][0].y), __float_as_uint(ua[mt][1].y),
                             bf0, bf1);
            }
        }
#pragma unroll
        for (int nt = 0; nt < 2; ++nt) {
            int colb = warp * 16 + nt * 8;
            int col0 = colb + tig * 2;
            float bb0 = fb2[band * 128 + col0];
            float bb1 = fb2[band * 128 + col0 + 1];
#pragma unroll
            for (int mt = 0; mt < 2; ++mt) {
                int r0 = mt * 16 + grp;
                zs[r0 * ZP + colb + off0]           = f2tf_f(acc[mt][nt][0] + bb0 + hs[r0 * HP + col0]);
                zs[r0 * ZP + colb + off0 + 2]       = f2tf_f(acc[mt][nt][1] + bb1 + hs[r0 * HP + col0 + 1]);
                zs[(r0 + 8) * ZP + colb + off0]     = f2tf_f(acc[mt][nt][2] + bb0 + hs[(r0 + 8) * HP + col0]);
                zs[(r0 + 8) * ZP + colb + off0 + 2] = f2tf_f(acc[mt][nt][3] + bb1 + hs[(r0 + 8) * HP + col0 + 1]);
            }
        }
    }
    __syncthreads();

    // ---- proj: p = band_out @ pw + pb -> g_p (tf32). Full unroll ----
    {
        float acc[2][4];
#pragma unroll
        for (int mt = 0; mt < 2; ++mt)
#pragma unroll
            for (int c = 0; c < 4; ++c) acc[mt][c] = 0.0f;

        const float* wbase = g_wp + ((((size_t)band * 16) * 8 + warp) * 32 + lane) * 2;
        const float* z0 = zs + grp * ZP + tig * 2;
#pragma unroll
        for (int kb = 0; kb < 16; ++kb) {
            const int k0 = kb * 8;
            float2 za[2][2];
#pragma unroll
            for (int mt = 0; mt < 2; ++mt) {
                const float* zm = z0 + mt * 16 * ZP + k0;
                za[mt][0] = *(const float2*)zm;
                za[mt][1] = *(const float2*)(zm + 8 * ZP);
            }
            const float2 wv = __ldg((const float2*)(wbase + (size_t)kb * 512));
            uint32_t bf0 = __float_as_uint(wv.x);
            uint32_t bf1 = __float_as_uint(wv.y);
#pragma unroll
            for (int mt = 0; mt < 2; ++mt)
                mma_tf32(acc[mt],
                         __float_as_uint(za[mt][0].x), __float_as_uint(za[mt][1].x),
                         __float_as_uint(za[mt][0].y), __float_as_uint(za[mt][1].y),
                         bf0, bf1);
        }
        int col0 = warp * 8 + tig * 2;
        float bb0 = pb[band * 64 + col0];
        float bb1 = pb[band * 64 + col0 + 1];
#pragma unroll
        for (int mt = 0; mt < 2; ++mt) {
            int r0 = mt * 16 + grp;
            float2 v0 = make_float2(f2tf_f(acc[mt][0] + bb0), f2tf_f(acc[mt][1] + bb1));
            float2 v1 = make_float2(f2tf_f(acc[mt][2] + bb0), f2tf_f(acc[mt][3] + bb1));
            *(float2*)&g_p[(((size_t)b * T_ + t0 + r0) * NB_ + band) * 64 + col0] = v0;
            *(float2*)&g_p[(((size_t)b * T_ + t0 + r0 + 8) * NB_ + band) * 64 + col0] = v1;
        }
    }
}

// ---------------------------------------------------------------------------
// Kernel 3 (tensor-core GEMM1): cat[32,448] @ mix_w1 -> gelu -> fp32 128->16.
// [R12 form, unchanged]
// ---------------------------------------------------------------------------
#define CP 452
#define MP 132

__global__ __launch_bounds__(256) void k_mix_tc(
    const float* __restrict__ mb1,
    const float* __restrict__ mw2, const float* __restrict__ mb2,
    float* __restrict__ out)
{
    extern __shared__ float sm[];
    float* cs = sm;                 // 32*452
    float* ms = sm + 32 * CP;       // 32*132

    const int bt0 = blockIdx.x * 32;
    const int tid = threadIdx.x;
    const int warp = tid >> 5, lane = tid & 31;
    const int grp = lane >> 2, tig = lane & 3;

    const float* cb = g_p + (size_t)bt0 * 448;
    for (int i = tid; i < 32 * 448; i += 256) {
        int r = i / 448, c = i - r * 448;
        cs[r * CP + c] = cb[i];
    }
    __syncthreads();

    {
        float acc[2][2][4];
#pragma unroll
        for (int mt = 0; mt < 2; ++mt)
#pragma unroll
            for (int nt = 0; nt < 2; ++nt)
#pragma unroll
                for (int c = 0; c < 4; ++c) acc[mt][nt][c] = 0.0f;

        const float* wbase = g_wm + ((size_t)warp * 32 + lane) * 4;
        const float* c0 = cs + grp * CP + tig;
#pragma unroll
        for (int kb = 0; kb < 56; ++kb) {
            const int k0 = kb * 8;
            uint32_t a[2][4];
#pragma unroll
            for (int mt = 0; mt < 2; ++mt) {
                const float* cm = c0 + mt * 16 * CP + k0;
                a[mt][0] = __float_as_uint(cm[0]);
                a[mt][1] = __float_as_uint(cm[8 * CP]);
                a[mt][2] = __float_as_uint(cm[4]);
                a[mt][3] = __float_as_uint(cm[8 * CP + 4]);
            }
            const float4 wv = __ldg((const float4*)(wbase + (size_t)kb * 1024));
#pragma unroll
            for (int nt = 0; nt < 2; ++nt) {
                uint32_t bf0 = __float_as_uint(nt ? wv.z : wv.x);
                uint32_t bf1 = __float_as_uint(nt ? wv.w : wv.y);
#pragma unroll
                for (int mt = 0; mt < 2; ++mt)
                    mma_tf32(acc[mt][nt], a[mt][0], a[mt][1], a[mt][2], a[mt][3], bf0, bf1);
            }
        }
#pragma unroll
        for (int nt = 0; nt < 2; ++nt) {
            int col0 = warp * 16 + nt * 8 + tig * 2;
            float bb0 = mb1[col0];
            float bb1 = mb1[col0 + 1];
#pragma unroll
            for (int mt = 0; mt < 2; ++mt) {
                int r0 = mt * 16 + grp;
                ms[r0 * MP + col0]           = gelu_exact(acc[mt][nt][0] + bb0);
                ms[r0 * MP + col0 + 1]       = gelu_exact(acc[mt][nt][1] + bb1);
                ms[(r0 + 8) * MP + col0]     = gelu_exact(acc[mt][nt][2] + bb0);
                ms[(r0 + 8) * MP + col0 + 1] = gelu_exact(acc[mt][nt][3] + bb1);
            }
        }
    }
    __syncthreads();

    {
        const int o = tid & 15, tb = tid >> 4;
        const float* wc = mw2 + o;
        const float bo = mb2[o];
#pragma unroll
        for (int h = 0; h < 2; ++h) {
            int tt = tb + h * 16;
            float acc = 0.0f;
#pragma unroll
            for (int e = 0; e < 128; e += 4) {
                float4 mv = *(const float4*)&ms[tt * MP + e];
                acc = fmaf(mv.x, wc[(e + 0) * 16], acc);
                acc = fmaf(mv.y, wc[(e + 1) * 16], acc);
                acc = fmaf(mv.z, wc[(e + 2) * 16], acc);
                acc = fmaf(mv.w, wc[(e + 3) * 16], acc);
            }
            out[(size_t)(bt0 + tt) * 16 + o] = acc + bo;
        }
    }
}

// ---------------------------------------------------------------------------
extern "C" void kernel_launch(void* const* d_in, const int* in_sizes, int n_in,
                              void* d_out, int out_size)
{
    const float* x      = (const float*)d_in[0];
    const float* conv_w = (const float*)d_in[1];
    const float* conv_b = (const float*)d_in[2];
    const float* dec_g  = (const float*)d_in[3];
    const float* dec_b  = (const float*)d_in[4];
    const float* n2_g   = (const float*)d_in[5];
    const float* n2_b   = (const float*)d_in[6];
    const float* ffn_w1 = (const float*)d_in[7];
    const float* ffn_b1 = (const float*)d_in[8];
    const float* ffn_w2 = (const float*)d_in[9];
    const float* ffn_b2 = (const float*)d_in[10];
    const float* proj_w = (const float*)d_in[11];
    const float* proj_b = (const float*)d_in[12];
    const float* mix_w1 = (const float*)d_in[13];
    const float* mix_b1 = (const float*)d_in[14];
    const float* mix_w2 = (const float*)d_in[15];
    const float* mix_b2 = (const float*)d_in[16];
    float* out = (float*)d_out;

    const int smem_fused = (8320 + 4224 + 4224) * 4;        // 67072 B
    const int smem_mix   = (32 * CP + 32 * MP) * 4;         // 74752 B
    cudaFuncSetAttribute(k_fused<31>, cudaFuncAttributeMaxDynamicSharedMemorySize, smem_fused);
    cudaFuncSetAttribute(k_fused<21>, cudaFuncAttributeMaxDynamicSharedMemorySize, smem_fused);
    cudaFuncSetAttribute(k_fused<15>, cudaFuncAttributeMaxDynamicSharedMemorySize, smem_fused);
    cudaFuncSetAttribute(k_fused<11>, cudaFuncAttributeMaxDynamicSharedMemorySize, smem_fused);
    cudaFuncSetAttribute(k_fused<7>,  cudaFuncAttributeMaxDynamicSharedMemorySize, smem_fused);
    cudaFuncSetAttribute(k_fused<5>,  cudaFuncAttributeMaxDynamicSharedMemorySize, smem_fused);
    cudaFuncSetAttribute(k_fused<3>,  cudaFuncAttributeMaxDynamicSharedMemorySize, smem_fused);
    cudaFuncSetAttribute(k_mix_tc, cudaFuncAttributeMaxDynamicSharedMemorySize, smem_mix);

    k_prep<<<512, 256>>>(conv_w, ffn_w1, ffn_w2, proj_w, mix_w1);

    dim3 gf(T_ / 32, B_);
    k_fused<31><<<gf, 256, smem_fused>>>(x, conv_b, dec_g, dec_b, n2_g, n2_b, ffn_b1, ffn_b2, proj_b, 0);
    k_fused<21><<<gf, 256, smem_fused>>>(x, conv_b, dec_g, dec_b, n2_g, n2_b, ffn_b1, ffn_b2, proj_b, 1);
    k_fused<15><<<gf, 256, smem_fused>>>(x, conv_b, dec_g, dec_b, n2_g, n2_b, ffn_b1, ffn_b2, proj_b, 2);
    k_fused<11><<<gf, 256, smem_fused>>>(x, conv_b, dec_g, dec_b, n2_g, n2_b, ffn_b1, ffn_b2, proj_b, 3);
    k_fused<7><<<gf, 256, smem_fused>>>(x, conv_b, dec_g, dec_b, n2_g, n2_b, ffn_b1, ffn_b2, proj_b, 4);
    k_fused<5><<<gf, 256, smem_fused>>>(x, conv_b, dec_g, dec_b, n2_g, n2_b, ffn_b1, ffn_b2, proj_b, 5);
    k_fused<3><<<gf, 256, smem_fused>>>(x, conv_b, dec_g, dec_b, n2_g, n2_b, ffn_b1, ffn_b2, proj_b, 6);

    dim3 g3((B_ * T_) / 32);
    k_mix_tc<<<g3, 256, smem_mix>>>(mix_b1, mix_w2, mix_b2, out);
}

// round 16
// speedup vs baseline: 1.4465x; 1.4465x over previous
#include <cuda_runtime.h>
#include <math.h>
#include <stdint.h>

#define NB_   7
#define S_    16
#define D_    128
#define B_    32
#define T_    2048
#define KMAX_ 31

__constant__ int c_ks[NB_] = {31, 21, 15, 11, 7, 5, 3};

// Scratch (device globals; no allocations allowed)
__device__ float g_p[(size_t)B_ * T_ * NB_ * 4 * S_];    // cat layout  [b][t][nb][4S]

// Fragment-major packed tf32 weights (permuted in k_prep)
#define NWC (NB_ * KMAX_ * S_ * D_)      // 444416
#define NW1 (NB_ * D_ * 2 * D_)          // 229376
#define NW2 (NB_ * 2 * D_ * D_)          // 229376
#define NWP (NB_ * D_ * 64)              // 57344
#define NWM (448 * 128)                  // 57344
__device__ float g_wc[NWC];
__device__ float g_w1[NW1];
__device__ float g_w2[NW2];
__device__ float g_wp[NWP];
__device__ float g_wm[NWM];

__device__ __forceinline__ float gelu_exact(float v) {
    return 0.5f * v * (1.0f + erff(v * 0.70710678118654752440f));
}

__device__ __forceinline__ uint32_t f2tf(float f) {
    uint32_t r;
    asm("cvt.rna.tf32.f32 %0, %1;" : "=r"(r) : "f"(f));
    return r;
}
__device__ __forceinline__ float f2tf_f(float f) { return __uint_as_float(f2tf(f)); }

__device__ __forceinline__ void mma_tf32(float c[4],
    uint32_t a0, uint32_t a1, uint32_t a2, uint32_t a3,
    uint32_t b0, uint32_t b1)
{
    asm volatile(
        "mma.sync.aligned.m16n8k8.row.col.f32.tf32.tf32.f32 "
        "{%0,%1,%2,%3},{%4,%5,%6,%7},{%8,%9},{%0,%1,%2,%3};"
        : "+f"(c[0]), "+f"(c[1]), "+f"(c[2]), "+f"(c[3])
        : "r"(a0), "r"(a1), "r"(a2), "r"(a3), "r"(b0), "r"(b1));
}

__device__ __forceinline__ void mma_tf32_p(float c[4], float2 lo, float2 hi,
    uint32_t b0, uint32_t b1)
{
    // lo = (row r0: k, k+4), hi = (row r0+8: k, k+4)
    mma_tf32(c, __float_as_uint(lo.x), __float_as_uint(hi.x),
                __float_as_uint(lo.y), __float_as_uint(hi.y), b0, b1);
}

// ---------------------------------------------------------------------------
// Kernel 0: tf32-round + permute all GEMM weights into fragment-major order.
// (identical to R12)
// ---------------------------------------------------------------------------
__global__ __launch_bounds__(256) void k_prep(
    const float* __restrict__ cw, const float* __restrict__ w1,
    const float* __restrict__ w2, const float* __restrict__ pw,
    const float* __restrict__ mw1)
{
    const int stride = gridDim.x * blockDim.x;
    const int i0 = blockIdx.x * blockDim.x + threadIdx.x;

    for (int i = i0; i < NW1; i += stride) {
        int pair = i & 1, nt = (i >> 1) & 3, lane = (i >> 3) & 31;
        int w = (i >> 8) & 7, kb = (i >> 11) & 15, band = i >> 15;
        int k = kb * 8 + (lane & 3) + pair * 4;
        int col = w * 32 + nt * 8 + (lane >> 2);
        g_w1[i] = f2tf_f(w1[((size_t)band * 128 + k) * 256 + col]);
    }
    for (int i = i0; i < NW2; i += stride) {
        int pair = i & 1, nt = (i >> 1) & 1, lane = (i >> 2) & 31;
        int w = (i >> 7) & 7, kb = (i >> 10) & 31, band = i >> 15;
        int k = kb * 8 + (lane & 3) + pair * 4;
        int col = w * 16 + nt * 8 + (lane >> 2);
        g_w2[i] = f2tf_f(w2[((size_t)band * 256 + k) * 128 + col]);
    }
    for (int i = i0; i < NWP; i += stride) {
        int pair = i & 1, lane = (i >> 1) & 31;
        int w = (i >> 6) & 7, kb = (i >> 9) & 15, band = i >> 13;
        int k = kb * 8 + (lane & 3) + pair * 4;
        int col = w * 8 + (lane >> 2);
        g_wp[i] = f2tf_f(pw[((size_t)band * 128 + k) * 64 + col]);
    }
    for (int i = i0; i < NWC; i += stride) {
        int sub = i & 1023;
        int pair = sub & 1, nt = (sub >> 1) & 1, lane = (sub >> 2) & 31, w = sub >> 7;
        int rest = i >> 10;
        int c8 = rest & 1; rest >>= 1;
        int k = rest % 31, band = rest / 31;
        int s = c8 * 8 + (lane & 3) + pair * 4;
        int col = w * 16 + nt * 8 + (lane >> 2);
        g_wc[i] = f2tf_f(cw[(((size_t)band * 31 + k) * 16 + s) * 128 + col]);
    }
    for (int i = i0; i < NWM; i += stride) {
        int pair = i & 1, nt = (i >> 1) & 1, lane = (i >> 2) & 31;
        int w = (i >> 7) & 7, kb = i >> 10;
        int k = kb * 8 + (lane & 3) + pair * 4;
        int col = w * 16 + nt * 8 + (lane >> 2);
        g_wm[i] = f2tf_f(mw1[(size_t)k * 128 + col]);
    }
}

// ---------------------------------------------------------------------------
// Kernel 1 (FUSED): conv -> LN1 -> LN2 -> GEMM1(gelu) -> GEMM2(+h) -> proj
// grid (T/32, B, NB), block 256. [R12 structure]
// Packed-pair columns in xs/zs/us: within each 8-group, p -> ((p&3)<<1)|(p>>2).
// Strides XSTR=40, ZP=136, UP=264 (all ≡8 mod 32 => LDS.64 conflict-free).
// smem: pool[8448] (xs 62*40=2480 | us 32*264), hs[32*132], zs[32*136]
// ---------------------------------------------------------------------------
#define XSTR 40
#define HP   132
#define ZP   136
#define UP   264

__global__ __launch_bounds__(256) void k_fused(
    const float* __restrict__ x,
    const float* __restrict__ conv_b,
    const float* __restrict__ dec_g, const float* __restrict__ dec_b,
    const float* __restrict__ n2_g, const float* __restrict__ n2_b,
    const float* __restrict__ fb1, const float* __restrict__ fb2,
    const float* __restrict__ pb)
{
    extern __shared__ float sm[];
    float* pool = sm;               // xs (62*40=2480) then us (32*264=8448)
    float* xs = pool;
    float* us = pool;
    float* hs = sm + 8448;          // 32*132 = 4224
    float* zs = sm + 12672;         // 32*136 = 4352

    const int band = blockIdx.z, b = blockIdx.y;
    const int t0 = blockIdx.x * 32;
    const int tid = threadIdx.x;
    const int warp = tid >> 5, lane = tid & 31;
    const int grp = lane >> 2, tig = lane & 3;
    const int off0 = ((tig & 1) << 2) | (tig >> 1);   // packed pos of col tig*2; pair at +2
    const int lanePk = (lane & ~7) | ((lane & 3) << 1) | ((lane >> 2) & 1);

    // ---- stage x window rows [t0-15, t0+46], tf32-rounded, packed cols ----
    const float* xb = x + (size_t)b * T_ * S_;
    for (int i = tid; i < 62 * S_; i += 256) {
        int row = i >> 4, s = i & 15;
        int gt = t0 + row - (KMAX_ / 2);
        float v = (gt >= 0 && gt < T_) ? xb[gt * S_ + s] : 0.0f;
        int sp = (s & 8) | ((s & 3) << 1) | ((s >> 2) & 1);
        xs[row * XSTR + sp] = f2tf_f(v);
    }
    __syncthreads();

    // ---- conv as mma (masked taps, dynamic loop), LDS.64 A-frags ----
    {
        float acc[2][2][4];
#pragma unroll
        for (int mt = 0; mt < 2; ++mt)
#pragma unroll
            for (int nt = 0; nt < 2; ++nt)
#pragma unroll
                for (int c = 0; c < 4; ++c) acc[mt][nt][c] = 0.0f;

        const int Kb = c_ks[band];
        const int off = (KMAX_ - Kb) >> 1;
        const float* xrow = xs + grp * XSTR + tig * 2;

        for (int k = off; k < off + Kb; ++k) {
#pragma unroll
            for (int c8 = 0; c8 < 2; ++c8) {
                float2 xa[2][2];
#pragma unroll
                for (int mt = 0; mt < 2; ++mt) {
                    const float* xr = xrow + (mt * 16 + k) * XSTR + c8 * 8;
                    xa[mt][0] = *(const float2*)xr;
                    xa[mt][1] = *(const float2*)(xr + 8 * XSTR);
                }
                const float4 wv = __ldg((const float4*)&g_wc[
                    (((((size_t)band * 31 + k) * 2 + c8) * 8 + warp) * 32 + lane) * 4]);
#pragma unroll
                for (int nt = 0; nt < 2; ++nt) {
                    uint32_t bf0 = __float_as_uint(nt ? wv.z : wv.x);
                    uint32_t bf1 = __float_as_uint(nt ? wv.w : wv.y);
#pragma unroll
                    for (int mt = 0; mt < 2; ++mt)
                        mma_tf32_p(acc[mt][nt], xa[mt][0], xa[mt][1], bf0, bf1);
                }
            }
        }

        // bias -> hs (row-major, pre-LN conv output)
#pragma unroll
        for (int nt = 0; nt < 2; ++nt) {
            int col0 = warp * 16 + nt * 8 + tig * 2;
            float bb0 = conv_b[band * D_ + col0];
            float bb1 = conv_b[band * D_ + col0 + 1];
#pragma unroll
            for (int mt = 0; mt < 2; ++mt) {
                int r0 = mt * 16 + grp;
                hs[r0 * HP + col0]           = acc[mt][nt][0] + bb0;
                hs[r0 * HP + col0 + 1]       = acc[mt][nt][1] + bb1;
                hs[(r0 + 8) * HP + col0]     = acc[mt][nt][2] + bb0;
                hs[(r0 + 8) * HP + col0 + 1] = acc[mt][nt][3] + bb1;
            }
        }
    }
    __syncthreads();   // hs complete; xs dead from here (pool becomes us)

    // ---- combined LN1 + LN2: hs := h (row-major), zs := tf32(z) (packed) ----
    {
        float g1v[4], b1v[4], g2v[4], b2v[4];
#pragma unroll
        for (int c = 0; c < 4; ++c) {
            g1v[c] = dec_g[band * D_ + lane + 32 * c];
            b1v[c] = dec_b[band * D_ + lane + 32 * c];
            g2v[c] = n2_g[band * D_ + lane + 32 * c];
            b2v[c] = n2_b[band * D_ + lane + 32 * c];
        }
        for (int i = 0; i < 4; ++i) {
            int tt = warp * 4 + i;
            float v[4]; float s = 0.0f;
#pragma unroll
            for (int c = 0; c < 4; ++c) { v[c] = hs[tt * HP + lane + 32 * c]; s += v[c]; }
#pragma unroll
            for (int o = 16; o; o >>= 1) s += __shfl_xor_sync(0xffffffffu, s, o);
            float mean = s * (1.0f / 128.0f);
            float q = 0.0f;
#pragma unroll
            for (int c = 0; c < 4; ++c) { float d0 = v[c] - mean; q = fmaf(d0, d0, q); }
#pragma unroll
            for (int o = 16; o; o >>= 1) q += __shfl_xor_sync(0xffffffffu, q, o);
            float rstd = rsqrtf(q * (1.0f / 128.0f) + 1e-5f);

            float hv[4]; float s2 = 0.0f;
#pragma unroll
            for (int c = 0; c < 4; ++c) {
                hv[c] = (v[c] - mean) * rstd * g1v[c] + b1v[c];
                hs[tt * HP + lane + 32 * c] = hv[c];
                s2 += hv[c];
            }
#pragma unroll
            for (int o = 16; o; o >>= 1) s2 += __shfl_xor_sync(0xffffffffu, s2, o);
            float mean2 = s2 * (1.0f / 128.0f);
            float q2 = 0.0f;
#pragma unroll
            for (int c = 0; c < 4; ++c) { float d0 = hv[c] - mean2; q2 = fmaf(d0, d0, q2); }
#pragma unroll
            for (int o = 16; o; o >>= 1) q2 += __shfl_xor_sync(0xffffffffu, q2, o);
            float rstd2 = rsqrtf(q2 * (1.0f / 128.0f) + 1e-5f);
#pragma unroll
            for (int c = 0; c < 4; ++c)
                zs[tt * ZP + lanePk + 32 * c] = f2tf_f((hv[c] - mean2) * rstd2 * g2v[c] + b2v[c]);
        }
    }
    __syncthreads();

    // ---- GEMM1: u = gelu(z @ W1 + b1). Full unroll, LDS.64 A-frags ----
    {
        float acc[2][4][4];
#pragma unroll
        for (int mt = 0; mt < 2; ++mt)
#pragma unroll
            for (int nt = 0; nt < 4; ++nt)
#pragma unroll
                for (int c = 0; c < 4; ++c) acc[mt][nt][c] = 0.0f;

        const float* wbase = g_w1 + ((((size_t)band * 16) * 8 + warp) * 32 + lane) * 8;
        const float* z0 = zs + grp * ZP + tig * 2;
#pragma unroll
        for (int kb = 0; kb < 16; ++kb) {
            const int k0 = kb * 8;
            float2 za[2][2];
#pragma unroll
            for (int mt = 0; mt < 2; ++mt) {
                const float* zm = z0 + mt * 16 * ZP + k0;
                za[mt][0] = *(const float2*)zm;
                za[mt][1] = *(const float2*)(zm + 8 * ZP);
            }
            const float4 w0 = __ldg((const float4*)(wbase + (size_t)kb * 2048));
            const float4 w1v = __ldg((const float4*)(wbase + (size_t)kb * 2048 + 4));
            const float wv[8] = {w0.x, w0.y, w0.z, w0.w, w1v.x, w1v.y, w1v.z, w1v.w};
#pragma unroll
            for (int nt = 0; nt < 4; ++nt) {
                uint32_t bf0 = __float_as_uint(wv[nt * 2]);
                uint32_t bf1 = __float_as_uint(wv[nt * 2 + 1]);
#pragma unroll
                for (int mt = 0; mt < 2; ++mt)
                    mma_tf32_p(acc[mt][nt], za[mt][0], za[mt][1], bf0, bf1);
            }
        }
#pragma unroll
        for (int nt = 0; nt < 4; ++nt) {
            int colb = warp * 32 + nt * 8;
            int col0 = colb + tig * 2;
            float bb0 = fb1[band * 256 + col0];
            float bb1 = fb1[band * 256 + col0 + 1];
#pragma unroll
            for (int mt = 0; mt < 2; ++mt) {
                int r0 = mt * 16 + grp;
                us[r0 * UP + colb + off0]           = f2tf_f(gelu_exact(acc[mt][nt][0] + bb0));
                us[r0 * UP + colb + off0 + 2]       = f2tf_f(gelu_exact(acc[mt][nt][1] + bb1));
                us[(r0 + 8) * UP + colb + off0]     = f2tf_f(gelu_exact(acc[mt][nt][2] + bb0));
                us[(r0 + 8) * UP + colb + off0 + 2] = f2tf_f(gelu_exact(acc[mt][nt][3] + bb1));
            }
        }
    }
    __syncthreads();

    // ---- GEMM2: band_out = h + u @ W2 + b2 -> zs (packed). Full unroll ----
    {
        float acc[2][2][4];
#pragma unroll
        for (int mt = 0; mt < 2; ++mt)
#pragma unroll
            for (int nt = 0; nt < 2; ++nt)
#pragma unroll
                for (int c = 0; c < 4; ++c) acc[mt][nt][c] = 0.0f;

        const float* wbase = g_w2 + ((((size_t)band * 32) * 8 + warp) * 32 + lane) * 4;
        const float* u0 = us + grp * UP + tig * 2;
#pragma unroll
        for (int kb = 0; kb < 32; ++kb) {
            const int k0 = kb * 8;
            float2 ua[2][2];
#pragma unroll
            for (int mt = 0; mt < 2; ++mt) {
                const float* um = u0 + mt * 16 * UP + k0;
                ua[mt][0] = *(const float2*)um;
                ua[mt][1] = *(const float2*)(um + 8 * UP);
            }
            const float4 wv = __ldg((const float4*)(wbase + (size_t)kb * 1024));
#pragma unroll
            for (int nt = 0; nt < 2; ++nt) {
                uint32_t bf0 = __float_as_uint(nt ? wv.z : wv.x);
                uint32_t bf1 = __float_as_uint(nt ? wv.w : wv.y);
#pragma unroll
                for (int mt = 0; mt < 2; ++mt)
                    mma_tf32_p(acc[mt][nt], ua[mt][0], ua[mt][1], bf0, bf1);
            }
        }
#pragma unroll
        for (int nt = 0; nt < 2; ++nt) {
            int colb = warp * 16 + nt * 8;
            int col0 = colb + tig * 2;
            float bb0 = fb2[band * 128 + col0];
            float bb1 = fb2[band * 128 + col0 + 1];
#pragma unroll
            for (int mt = 0; mt < 2; ++mt) {
                int r0 = mt * 16 + grp;
                zs[r0 * ZP + colb + off0]           = f2tf_f(acc[mt][nt][0] + bb0 + hs[r0 * HP + col0]);
                zs[r0 * ZP + colb + off0 + 2]       = f2tf_f(acc[mt][nt][1] + bb1 + hs[r0 * HP + col0 + 1]);
                zs[(r0 + 8) * ZP + colb + off0]     = f2tf_f(acc[mt][nt][2] + bb0 + hs[(r0 + 8) * HP + col0]);
                zs[(r0 + 8) * ZP + colb + off0 + 2] = f2tf_f(acc[mt][nt][3] + bb1 + hs[(r0 + 8) * HP + col0 + 1]);
            }
        }
    }
    __syncthreads();

    // ---- proj: p = band_out @ pw + pb -> g_p (tf32). Full unroll ----
    {
        float acc[2][4];
#pragma unroll
        for (int mt = 0; mt < 2; ++mt)
#pragma unroll
            for (int c = 0; c < 4; ++c) acc[mt][c] = 0.0f;

        const float* wbase = g_wp + ((((size_t)band * 16) * 8 + warp) * 32 + lane) * 2;
        const float* z0 = zs + grp * ZP + tig * 2;
#pragma unroll
        for (int kb = 0; kb < 16; ++kb) {
            const int k0 = kb * 8;
            float2 za[2][2];
#pragma unroll
            for (int mt = 0; mt < 2; ++mt) {
                const float* zm = z0 + mt * 16 * ZP + k0;
                za[mt][0] = *(const float2*)zm;
                za[mt][1] = *(const float2*)(zm + 8 * ZP);
            }
            const float2 wv = __ldg((const float2*)(wbase + (size_t)kb * 512));
            uint32_t bf0 = __float_as_uint(wv.x);
            uint32_t bf1 = __float_as_uint(wv.y);
#pragma unroll
            for (int mt = 0; mt < 2; ++mt)
                mma_tf32_p(acc[mt], za[mt][0], za[mt][1], bf0, bf1);
        }
        int col0 = warp * 8 + tig * 2;
        float bb0 = pb[band * 64 + col0];
        float bb1 = pb[band * 64 + col0 + 1];
#pragma unroll
        for (int mt = 0; mt < 2; ++mt) {
            int r0 = mt * 16 + grp;
            float2 v0 = make_float2(f2tf_f(acc[mt][0] + bb0), f2tf_f(acc[mt][1] + bb1));
            float2 v1 = make_float2(f2tf_f(acc[mt][2] + bb0), f2tf_f(acc[mt][3] + bb1));
            *(float2*)&g_p[(((size_t)b * T_ + t0 + r0) * NB_ + band) * 64 + col0] = v0;
            *(float2*)&g_p[(((size_t)b * T_ + t0 + r0 + 8) * NB_ + band) * 64 + col0] = v1;
        }
    }
}

// ---------------------------------------------------------------------------
// Kernel 3 (tensor-core GEMM1): cat[32,448] @ mix_w1 -> gelu -> fp32 128->16.
// Packed-pair cs (CP=456 ≡8 mod 32), LDS.64 A-frags. Full unroll.
// ---------------------------------------------------------------------------
#define CP 456
#define MP 132

__global__ __launch_bounds__(256) void k_mix_tc(
    const float* __restrict__ mb1,
    const float* __restrict__ mw2, const float* __restrict__ mb2,
    float* __restrict__ out)
{
    extern __shared__ float sm[];
    float* cs = sm;                 // 32*456 = 14592 (packed cols)
    float* ms = sm + 32 * CP;       // 32*132

    const int bt0 = blockIdx.x * 32;
    const int tid = threadIdx.x;
    const int warp = tid >> 5, lane = tid & 31;
    const int grp = lane >> 2, tig = lane & 3;

    const float* cb = g_p + (size_t)bt0 * 448;
    for (int i = tid; i < 32 * 448; i += 256) {
        int r = i / 448, c = i - r * 448;
        int cp = (c & ~7) | ((c & 3) << 1) | ((c >> 2) & 1);
        cs[r * CP + cp] = cb[i];
    }
    __syncthreads();

    {
        float acc[2][2][4];
#pragma unroll
        for (int mt = 0; mt < 2; ++mt)
#pragma unroll
            for (int nt = 0; nt < 2; ++nt)
#pragma unroll
                for (int c = 0; c < 4; ++c) acc[mt][nt][c] = 0.0f;

        const float* wbase = g_wm + ((size_t)warp * 32 + lane) * 4;
        const float* c0 = cs + grp * CP + tig * 2;
#pragma unroll
        for (int kb = 0; kb < 56; ++kb) {
            const int k0 = kb * 8;
            float2 ca[2][2];
#pragma unroll
            for (int mt = 0; mt < 2; ++mt) {
                const float* cm = c0 + mt * 16 * CP + k0;
                ca[mt][0] = *(const float2*)cm;
                ca[mt][1] = *(const float2*)(cm + 8 * CP);
            }
            const float4 wv = __ldg((const float4*)(wbase + (size_t)kb * 1024));
#pragma unroll
            for (int nt = 0; nt < 2; ++nt) {
                uint32_t bf0 = __float_as_uint(nt ? wv.z : wv.x);
                uint32_t bf1 = __float_as_uint(nt ? wv.w : wv.y);
#pragma unroll
                for (int mt = 0; mt < 2; ++mt)
                    mma_tf32_p(acc[mt][nt], ca[mt][0], ca[mt][1], bf0, bf1);
            }
        }
#pragma unroll
        for (int nt = 0; nt < 2; ++nt) {
            int col0 = warp * 16 + nt * 8 + tig * 2;
            float bb0 = mb1[col0];
            float bb1 = mb1[col0 + 1];
#pragma unroll
            for (int mt = 0; mt < 2; ++mt) {
                int r0 = mt * 16 + grp;
                ms[r0 * MP + col0]           = gelu_exact(acc[mt][nt][0] + bb0);
                ms[r0 * MP + col0 + 1]       = gelu_exact(acc[mt][nt][1] + bb1);
                ms[(r0 + 8) * MP + col0]     = gelu_exact(acc[mt][nt][2] + bb0);
                ms[(r0 + 8) * MP + col0 + 1] = gelu_exact(acc[mt][nt][3] + bb1);
            }
        }
    }
    __syncthreads();

    {
        const int o = tid & 15, tb = tid >> 4;
        const float* wc = mw2 + o;
        const float bo = mb2[o];
#pragma unroll
        for (int h = 0; h < 2; ++h) {
            int tt = tb + h * 16;
            float acc = 0.0f;
#pragma unroll
            for (int e = 0; e < 128; e += 4) {
                float4 mv = *(const float4*)&ms[tt * MP + e];
                acc = fmaf(mv.x, wc[(e + 0) * 16], acc);
                acc = fmaf(mv.y, wc[(e + 1) * 16], acc);
                acc = fmaf(mv.z, wc[(e + 2) * 16], acc);
                acc = fmaf(mv.w, wc[(e + 3) * 16], acc);
            }
            out[(size_t)(bt0 + tt) * 16 + o] = acc + bo;
        }
    }
}

// ---------------------------------------------------------------------------
extern "C" void kernel_launch(void* const* d_in, const int* in_sizes, int n_in,
                              void* d_out, int out_size)
{
    const float* x      = (const float*)d_in[0];
    const float* conv_w = (const float*)d_in[1];
    const float* conv_b = (const float*)d_in[2];
    const float* dec_g  = (const float*)d_in[3];
    const float* dec_b  = (const float*)d_in[4];
    const float* n2_g   = (const float*)d_in[5];
    const float* n2_b   = (const float*)d_in[6];
    const float* ffn_w1 = (const float*)d_in[7];
    const float* ffn_b1 = (const float*)d_in[8];
    const float* ffn_w2 = (const float*)d_in[9];
    const float* ffn_b2 = (const float*)d_in[10];
    const float* proj_w = (const float*)d_in[11];
    const float* proj_b = (const float*)d_in[12];
    const float* mix_w1 = (const float*)d_in[13];
    const float* mix_b1 = (const float*)d_in[14];
    const float* mix_w2 = (const float*)d_in[15];
    const float* mix_b2 = (const float*)d_in[16];
    float* out = (float*)d_out;

    const int smem_fused = (8448 + 4224 + 4352) * 4;        // 68096 B
    const int smem_mix   = (32 * CP + 32 * MP) * 4;         // 75264 B
    cudaFuncSetAttribute(k_fused, cudaFuncAttributeMaxDynamicSharedMemorySize, smem_fused);
    cudaFuncSetAttribute(k_mix_tc, cudaFuncAttributeMaxDynamicSharedMemorySize, smem_mix);

    k_prep<<<512, 256>>>(conv_w, ffn_w1, ffn_w2, proj_w, mix_w1);

    dim3 g1(T_ / 32, B_, NB_);
    k_fused<<<g1, 256, smem_fused>>>(x, conv_b, dec_g, dec_b, n2_g, n2_b,
                                     ffn_b1, ffn_b2, proj_b);

    dim3 g3((B_ * T_) / 32);
    k_mix_tc<<<g3, 256, smem_mix>>>(mix_b1, mix_w2, mix_b2, out);
}

// round 17
// speedup vs baseline: 1.7878x; 1.2359x over previous
#include <cuda_runtime.h>
#include <cuda_bf16.h>
#include <math.h>
#include <stdint.h>

#define NB_   7
#define S_    16
#define D_    128
#define B_    32
#define T_    2048
#define KMAX_ 31

__constant__ int c_ks[NB_] = {31, 21, 15, 11, 7, 5, 3};

// Scratch (device globals; no allocations allowed)
__device__ float g_p[(size_t)B_ * T_ * NB_ * 4 * S_];    // cat layout  [b][t][nb][4S]

// Fragment-major packed weights
#define NWC  (NB_ * KMAX_ * S_ * D_)     // 444416 (tf32 floats, conv)
#define NWP  (NB_ * D_ * 64)             // 57344  (tf32 floats, proj)
#define NWM  (448 * 128)                 // 57344  (tf32 floats, mix)
#define NW1B (NB_ * 8 * 8 * 32 * 8)      // 114688 u32 (bf16x2, ffn W1)
#define NW2B (NB_ * 16 * 8 * 32 * 4)     // 114688 u32 (bf16x2, ffn W2)
__device__ float    g_wc[NWC];
__device__ float    g_wp[NWP];
__device__ float    g_wm[NWM];
__device__ uint32_t g_w1b[NW1B];
__device__ uint32_t g_w2b[NW2B];

__device__ __forceinline__ float gelu_exact(float v) {
    return 0.5f * v * (1.0f + erff(v * 0.70710678118654752440f));
}

__device__ __forceinline__ uint32_t f2tf(float f) {
    uint32_t r;
    asm("cvt.rna.tf32.f32 %0, %1;" : "=r"(r) : "f"(f));
    return r;
}
__device__ __forceinline__ float f2tf_f(float f) { return __uint_as_float(f2tf(f)); }

// pack (lo, hi) floats into bf16x2 word {hi:lo}
__device__ __forceinline__ uint32_t packbf(float lo, float hi) {
    uint32_t d;
    asm("cvt.rn.bf16x2.f32 %0, %1, %2;" : "=r"(d) : "f"(hi), "f"(lo));
    return d;
}

__device__ __forceinline__ void mma_tf32(float c[4],
    uint32_t a0, uint32_t a1, uint32_t a2, uint32_t a3,
    uint32_t b0, uint32_t b1)
{
    asm volatile(
        "mma.sync.aligned.m16n8k8.row.col.f32.tf32.tf32.f32 "
        "{%0,%1,%2,%3},{%4,%5,%6,%7},{%8,%9},{%0,%1,%2,%3};"
        : "+f"(c[0]), "+f"(c[1]), "+f"(c[2]), "+f"(c[3])
        : "r"(a0), "r"(a1), "r"(a2), "r"(a3), "r"(b0), "r"(b1));
}

__device__ __forceinline__ void mma_tf32_p(float c[4], float2 lo, float2 hi,
    uint32_t b0, uint32_t b1)
{
    mma_tf32(c, __float_as_uint(lo.x), __float_as_uint(hi.x),
                __float_as_uint(lo.y), __float_as_uint(hi.y), b0, b1);
}

__device__ __forceinline__ void mma_bf16(float c[4],
    uint32_t a0, uint32_t a1, uint32_t a2, uint32_t a3,
    uint32_t b0, uint32_t b1)
{
    asm volatile(
        "mma.sync.aligned.m16n8k16.row.col.f32.bf16.bf16.f32 "
        "{%0,%1,%2,%3},{%4,%5,%6,%7},{%8,%9},{%0,%1,%2,%3};"
        : "+f"(c[0]), "+f"(c[1]), "+f"(c[2]), "+f"(c[3])
        : "r"(a0), "r"(a1), "r"(a2), "r"(a3), "r"(b0), "r"(b1));
}

// ---------------------------------------------------------------------------
// Kernel 0: round + permute all weights into fragment-major order.
// conv/proj/mix: tf32 floats (R16 layouts). W1/W2: bf16x2 words, m16n8k16 frags.
// ---------------------------------------------------------------------------
__global__ __launch_bounds__(256) void k_prep(
    const float* __restrict__ cw, const float* __restrict__ w1,
    const float* __restrict__ w2, const float* __restrict__ pw,
    const float* __restrict__ mw1)
{
    const int stride = gridDim.x * blockDim.x;
    const int i0 = blockIdx.x * blockDim.x + threadIdx.x;

    // W1 bf16: i = ((((band*8+kb)*8+w)*32+lane)*8 + nt*2 + half)
    for (int i = i0; i < NW1B; i += stride) {
        int half = i & 1, nt = (i >> 1) & 3, lane = (i >> 3) & 31;
        int w = (i >> 8) & 7, kb = (i >> 11) & 7, band = i >> 14;
        int tig = lane & 3, grp = lane >> 2;
        int k0 = kb * 16 + tig * 2 + half * 8;
        int col = w * 32 + nt * 8 + grp;
        float lo = w1[((size_t)band * 128 + k0) * 256 + col];
        float hi = w1[((size_t)band * 128 + k0 + 1) * 256 + col];
        g_w1b[i] = packbf(lo, hi);
    }
    // W2 bf16: i = ((((band*16+kb)*8+w)*32+lane)*4 + nt*2 + half)
    for (int i = i0; i < NW2B; i += stride) {
        int half = i & 1, nt = (i >> 1) & 1, lane = (i >> 2) & 31;
        int w = (i >> 7) & 7, kb = (i >> 10) & 15, band = i >> 14;
        int tig = lane & 3, grp = lane >> 2;
        int k0 = kb * 16 + tig * 2 + half * 8;
        int col = w * 16 + nt * 8 + grp;
        float lo = w2[((size_t)band * 256 + k0) * 128 + col];
        float hi = w2[((size_t)band * 256 + k0 + 1) * 128 + col];
        g_w2b[i] = packbf(lo, hi);
    }
    for (int i = i0; i < NWP; i += stride) {
        int pair = i & 1, lane = (i >> 1) & 31;
        int w = (i >> 6) & 7, kb = (i >> 9) & 15, band = i >> 13;
        int k = kb * 8 + (lane & 3) + pair * 4;
        int col = w * 8 + (lane >> 2);
        g_wp[i] = f2tf_f(pw[((size_t)band * 128 + k) * 64 + col]);
    }
    for (int i = i0; i < NWC; i += stride) {
        int sub = i & 1023;
        int pair = sub & 1, nt = (sub >> 1) & 1, lane = (sub >> 2) & 31, w = sub >> 7;
        int rest = i >> 10;
        int c8 = rest & 1; rest >>= 1;
        int k = rest % 31, band = rest / 31;
        int s = c8 * 8 + (lane & 3) + pair * 4;
        int col = w * 16 + nt * 8 + (lane >> 2);
        g_wc[i] = f2tf_f(cw[(((size_t)band * 31 + k) * 16 + s) * 128 + col]);
    }
    for (int i = i0; i < NWM; i += stride) {
        int pair = i & 1, nt = (i >> 1) & 1, lane = (i >> 2) & 31;
        int w = (i >> 7) & 7, kb = i >> 10;
        int k = kb * 8 + (lane & 3) + pair * 4;
        int col = w * 16 + nt * 8 + (lane >> 2);
        g_wm[i] = f2tf_f(mw1[(size_t)k * 128 + col]);
    }
}

// ---------------------------------------------------------------------------
// Kernel 1 (FUSED): conv(tf32) -> LN1 -> LN2 -> GEMM1(bf16,gelu) ->
//                   GEMM2(bf16,+h) -> proj(tf32) -> g_p
// grid (T/32, B, NB), block 256.
// smem (float units): pool[4352] (xs float 2480 | us_b u32 32*136),
//   hs[4224] (32*132 row-major float), zs[4352] (32*136 packed float),
//   zb[2304] (u32, 32*72 bf16x2 words)   => 60928 B total
// ---------------------------------------------------------------------------
#define XSTR 40
#define HP   132
#define ZP   136
#define ZBW  72     // zb words per row (64 + pad, ≡8 mod 32)
#define UBW  136    // us_b words per row (128 + pad, ≡8 mod 32)

__global__ __launch_bounds__(256) void k_fused(
    const float* __restrict__ x,
    const float* __restrict__ conv_b,
    const float* __restrict__ dec_g, const float* __restrict__ dec_b,
    const float* __restrict__ n2_g, const float* __restrict__ n2_b,
    const float* __restrict__ fb1, const float* __restrict__ fb2,
    const float* __restrict__ pb)
{
    extern __shared__ float sm[];
    float*    xs   = sm;                          // conv staging (2480 fl)
    uint32_t* us_b = (uint32_t*)sm;               // bf16 u tile (4352 w) — aliases xs
    float*    hs   = sm + 4352;                   // 32*132
    float*    zs   = sm + 8576;                   // 32*136 (band_out, packed tf32)
    uint32_t* zb   = (uint32_t*)(sm + 12928);     // 32*72 bf16x2 z words

    const int band = blockIdx.z, b = blockIdx.y;
    const int t0 = blockIdx.x * 32;
    const int tid = threadIdx.x;
    const int warp = tid >> 5, lane = tid & 31;
    const int grp = lane >> 2, tig = lane & 3;
    const int off0 = ((tig & 1) << 2) | (tig >> 1);   // packed float-col pos (proj path)
    const int lanePkW = (lane & ~7) | ((lane & 3) << 1) | ((lane >> 2) & 1); // word perm

    // ---- stage x window rows [t0-15, t0+46], tf32-rounded, packed cols ----
    const float* xb = x + (size_t)b * T_ * S_;
    for (int i = tid; i < 62 * S_; i += 256) {
        int row = i >> 4, s = i & 15;
        int gt = t0 + row - (KMAX_ / 2);
        float v = (gt >= 0 && gt < T_) ? xb[gt * S_ + s] : 0.0f;
        int sp = (s & 8) | ((s & 3) << 1) | ((s >> 2) & 1);
        xs[row * XSTR + sp] = f2tf_f(v);
    }
    __syncthreads();

    // ---- conv as tf32 mma (masked taps), LDS.64 A-frags [R16 form] ----
    {
        float acc[2][2][4];
#pragma unroll
        for (int mt = 0; mt < 2; ++mt)
#pragma unroll
            for (int nt = 0; nt < 2; ++nt)
#pragma unroll
                for (int c = 0; c < 4; ++c) acc[mt][nt][c] = 0.0f;

        const int Kb = c_ks[band];
        const int off = (KMAX_ - Kb) >> 1;
        const float* xrow = xs + grp * XSTR + tig * 2;

        for (int k = off; k < off + Kb; ++k) {
#pragma unroll
            for (int c8 = 0; c8 < 2; ++c8) {
                float2 xa[2][2];
#pragma unroll
                for (int mt = 0; mt < 2; ++mt) {
                    const float* xr = xrow + (mt * 16 + k) * XSTR + c8 * 8;
                    xa[mt][0] = *(const float2*)xr;
                    xa[mt][1] = *(const float2*)(xr + 8 * XSTR);
                }
                const float4 wv = __ldg((const float4*)&g_wc[
                    (((((size_t)band * 31 + k) * 2 + c8) * 8 + warp) * 32 + lane) * 4]);
#pragma unroll
                for (int nt = 0; nt < 2; ++nt) {
                    uint32_t bf0 = __float_as_uint(nt ? wv.z : wv.x);
                    uint32_t bf1 = __float_as_uint(nt ? wv.w : wv.y);
#pragma unroll
                    for (int mt = 0; mt < 2; ++mt)
                        mma_tf32_p(acc[mt][nt], xa[mt][0], xa[mt][1], bf0, bf1);
                }
            }
        }

        // bias -> hs (row-major, pre-LN conv output)
#pragma unroll
        for (int nt = 0; nt < 2; ++nt) {
            int col0 = warp * 16 + nt * 8 + tig * 2;
            float bb0 = conv_b[band * D_ + col0];
            float bb1 = conv_b[band * D_ + col0 + 1];
#pragma unroll
            for (int mt = 0; mt < 2; ++mt) {
                int r0 = mt * 16 + grp;
                hs[r0 * HP + col0]           = acc[mt][nt][0] + bb0;
                hs[r0 * HP + col0 + 1]       = acc[mt][nt][1] + bb1;
                hs[(r0 + 8) * HP + col0]     = acc[mt][nt][2] + bb0;
                hs[(r0 + 8) * HP + col0 + 1] = acc[mt][nt][3] + bb1;
            }
        }
    }
    __syncthreads();   // hs complete; xs dead (pool becomes us_b)

    // ---- LN1 + LN2 (pairwise): hs := h (row-major), zb := bf16x2(z) ----
    {
        float2 g1a = *(const float2*)&dec_g[band * D_ + 2 * lane];
        float2 g1b = *(const float2*)&dec_g[band * D_ + 2 * lane + 64];
        float2 b1a = *(const float2*)&dec_b[band * D_ + 2 * lane];
        float2 b1b = *(const float2*)&dec_b[band * D_ + 2 * lane + 64];
        float2 g2a = *(const float2*)&n2_g[band * D_ + 2 * lane];
        float2 g2b = *(const float2*)&n2_g[band * D_ + 2 * lane + 64];
        float2 b2a = *(const float2*)&n2_b[band * D_ + 2 * lane];
        float2 b2b = *(const float2*)&n2_b[band * D_ + 2 * lane + 64];

        for (int i = 0; i < 4; ++i) {
            int tt = warp * 4 + i;
            float2 vA = *(const float2*)&hs[tt * HP + 2 * lane];
            float2 vB = *(const float2*)&hs[tt * HP + 2 * lane + 64];
            float s = vA.x + vA.y + vB.x + vB.y;
#pragma unroll
            for (int o = 16; o; o >>= 1) s += __shfl_xor_sync(0xffffffffu, s, o);
            float mean = s * (1.0f / 128.0f);
            float q = (vA.x - mean) * (vA.x - mean) + (vA.y - mean) * (vA.y - mean)
                    + (vB.x - mean) * (vB.x - mean) + (vB.y - mean) * (vB.y - mean);
#pragma unroll
            for (int o = 16; o; o >>= 1) q += __shfl_xor_sync(0xffffffffu, q, o);
            float rstd = rsqrtf(q * (1.0f / 128.0f) + 1e-5f);

            float2 hA, hB;
            hA.x = (vA.x - mean) * rstd * g1a.x + b1a.x;
            hA.y = (vA.y - mean) * rstd * g1a.y + b1a.y;
            hB.x = (vB.x - mean) * rstd * g1b.x + b1b.x;
            hB.y = (vB.y - mean) * rstd * g1b.y + b1b.y;
            *(float2*)&hs[tt * HP + 2 * lane]      = hA;
            *(float2*)&hs[tt * HP + 2 * lane + 64] = hB;

            float s2 = hA.x + hA.y + hB.x + hB.y;
#pragma unroll
            for (int o = 16; o; o >>= 1) s2 += __shfl_xor_sync(0xffffffffu, s2, o);
            float mean2 = s2 * (1.0f / 128.0f);
            float q2 = (hA.x - mean2) * (hA.x - mean2) + (hA.y - mean2) * (hA.y - mean2)
                     + (hB.x - mean2) * (hB.x - mean2) + (hB.y - mean2) * (hB.y - mean2);
#pragma unroll
            for (int o = 16; o; o >>= 1) q2 += __shfl_xor_sync(0xffffffffu, q2, o);
            float rstd2 = rsqrtf(q2 * (1.0f / 128.0f) + 1e-5f);

            zb[tt * ZBW + lanePkW] = packbf(
                (hA.x - mean2) * rstd2 * g2a.x + b2a.x,
                (hA.y - mean2) * rstd2 * g2a.y + b2a.y);
            zb[tt * ZBW + lanePkW + 32] = packbf(
                (hB.x - mean2) * rstd2 * g2b.x + b2b.x,
                (hB.y - mean2) * rstd2 * g2b.y + b2b.y);
        }
    }
    __syncthreads();

    // ---- GEMM1 (bf16 m16n8k16): u = gelu(z @ W1 + b1) -> us_b ----
    {
        float acc[2][4][4];
#pragma unroll
        for (int mt = 0; mt < 2; ++mt)
#pragma unroll
            for (int nt = 0; nt < 4; ++nt)
#pragma unroll
                for (int c = 0; c < 4; ++c) acc[mt][nt][c] = 0.0f;

        const uint32_t* wbase = g_w1b + ((((size_t)band * 8) * 8 + warp) * 32 + lane) * 8;
        const uint32_t* z0 = zb + grp * ZBW + 2 * tig;
#pragma unroll
        for (int kb = 0; kb < 8; ++kb) {
            uint2 za[2][2];
#pragma unroll
            for (int mt = 0; mt < 2; ++mt) {
                const uint32_t* zr = z0 + mt * 16 * ZBW + kb * 8;
                za[mt][0] = *(const uint2*)zr;               // row grp:   {kLo, kHi}
                za[mt][1] = *(const uint2*)(zr + 8 * ZBW);   // row grp+8
            }
            const uint4 wA = __ldg((const uint4*)(wbase + (size_t)kb * 2048));
            const uint4 wB = __ldg((const uint4*)(wbase + (size_t)kb * 2048 + 4));
            const uint32_t wv[8] = {wA.x, wA.y, wA.z, wA.w, wB.x, wB.y, wB.z, wB.w};
#pragma unroll
            for (int nt = 0; nt < 4; ++nt) {
#pragma unroll
                for (int mt = 0; mt < 2; ++mt)
                    mma_bf16(acc[mt][nt], za[mt][0].x, za[mt][1].x,
                             za[mt][0].y, za[mt][1].y, wv[nt * 2], wv[nt * 2 + 1]);
            }
        }
#pragma unroll
        for (int nt = 0; nt < 4; ++nt) {
            int col0 = warp * 32 + nt * 8 + tig * 2;
            float bb0 = fb1[band * 256 + col0];
            float bb1 = fb1[band * 256 + col0 + 1];
            int uw = warp * 16 + (nt >> 1) * 8 + ((nt & 1) ? 2 * tig + 1 : 2 * tig);
#pragma unroll
            for (int mt = 0; mt < 2; ++mt) {
                int r0 = mt * 16 + grp;
                us_b[r0 * UBW + uw] = packbf(gelu_exact(acc[mt][nt][0] + bb0),
                                             gelu_exact(acc[mt][nt][1] + bb1));
                us_b[(r0 + 8) * UBW + uw] = packbf(gelu_exact(acc[mt][nt][2] + bb0),
                                                   gelu_exact(acc[mt][nt][3] + bb1));
            }
        }
    }
    __syncthreads();

    // ---- GEMM2 (bf16): band_out = h + u @ W2 + b2 -> zs (packed tf32) ----
    {
        float acc[2][2][4];
#pragma unroll
        for (int mt = 0; mt < 2; ++mt)
#pragma unroll
            for (int nt = 0; nt < 2; ++nt)
#pragma unroll
                for (int c = 0; c < 4; ++c) acc[mt][nt][c] = 0.0f;

        const uint32_t* wbase = g_w2b + ((((size_t)band * 16) * 8 + warp) * 32 + lane) * 4;
        const uint32_t* u0 = us_b + grp * UBW + 2 * tig;
#pragma unroll
        for (int kb = 0; kb < 16; ++kb) {
            uint2 ua[2][2];
#pragma unroll
            for (int mt = 0; mt < 2; ++mt) {
                const uint32_t* ur = u0 + mt * 16 * UBW + kb * 8;
                ua[mt][0] = *(const uint2*)ur;
                ua[mt][1] = *(const uint2*)(ur + 8 * UBW);
            }
            const uint4 wv = __ldg((const uint4*)(wbase + (size_t)kb * 1024));
#pragma unroll
            for (int nt = 0; nt < 2; ++nt) {
                uint32_t b0 = nt ? wv.z : wv.x;
                uint32_t b1 = nt ? wv.w : wv.y;
#pragma unroll
                for (int mt = 0; mt < 2; ++mt)
                    mma_bf16(acc[mt][nt], ua[mt][0].x, ua[mt][1].x,
                             ua[mt][0].y, ua[mt][1].y, b0, b1);
            }
        }
#pragma unroll
        for (int nt = 0; nt < 2; ++nt) {
            int colb = warp * 16 + nt * 8;
            int col0 = colb + tig * 2;
            float bb0 = fb2[band * 128 + col0];
            float bb1 = fb2[band * 128 + col0 + 1];
#pragma unroll
            for (int mt = 0; mt < 2; ++mt) {
                int r0 = mt * 16 + grp;
                zs[r0 * ZP + colb + off0]           = f2tf_f(acc[mt][nt][0] + bb0 + hs[r0 * HP + col0]);
                zs[r0 * ZP + colb + off0 + 2]       = f2tf_f(acc[mt][nt][1] + bb1 + hs[r0 * HP + col0 + 1]);
                zs[(r0 + 8) * ZP + colb + off0]     = f2tf_f(acc[mt][nt][2] + bb0 + hs[(r0 + 8) * HP + col0]);
                zs[(r0 + 8) * ZP + colb + off0 + 2] = f2tf_f(acc[mt][nt][3] + bb1 + hs[(r0 + 8) * HP + col0 + 1]);
            }
        }
    }
    __syncthreads();

    // ---- proj (tf32): p = band_out @ pw + pb -> g_p [R16 form] ----
    {
        float acc[2][4];
#pragma unroll
        for (int mt = 0; mt < 2; ++mt)
#pragma unroll
            for (int c = 0; c < 4; ++c) acc[mt][c] = 0.0f;

        const float* wbase = g_wp + ((((size_t)band * 16) * 8 + warp) * 32 + lane) * 2;
        const float* z0 = zs + grp * ZP + tig * 2;
#pragma unroll
        for (int kb = 0; kb < 16; ++kb) {
            const int k0 = kb * 8;
            float2 za[2][2];
#pragma unroll
            for (int mt = 0; mt < 2; ++mt) {
                const float* zm = z0 + mt * 16 * ZP + k0;
                za[mt][0] = *(const float2*)zm;
                za[mt][1] = *(const float2*)(zm + 8 * ZP);
            }
            const float2 wv = __ldg((const float2*)(wbase + (size_t)kb * 512));
            uint32_t bf0 = __float_as_uint(wv.x);
            uint32_t bf1 = __float_as_uint(wv.y);
#pragma unroll
            for (int mt = 0; mt < 2; ++mt)
                mma_tf32_p(acc[mt], za[mt][0], za[mt][1], bf0, bf1);
        }
        int col0 = warp * 8 + tig * 2;
        float bb0 = pb[band * 64 + col0];
        float bb1 = pb[band * 64 + col0 + 1];
#pragma unroll
        for (int mt = 0; mt < 2; ++mt) {
            int r0 = mt * 16 + grp;
            float2 v0 = make_float2(f2tf_f(acc[mt][0] + bb0), f2tf_f(acc[mt][1] + bb1));
            float2 v1 = make_float2(f2tf_f(acc[mt][2] + bb0), f2tf_f(acc[mt][3] + bb1));
            *(float2*)&g_p[(((size_t)b * T_ + t0 + r0) * NB_ + band) * 64 + col0] = v0;
            *(float2*)&g_p[(((size_t)b * T_ + t0 + r0 + 8) * NB_ + band) * 64 + col0] = v1;
        }
    }
}

// ---------------------------------------------------------------------------
// Kernel 3 (tf32): cat[32,448] @ mix_w1 -> gelu -> fp32 128->16. [R16 form]
// ---------------------------------------------------------------------------
#define CP 456
#define MP 132

__global__ __launch_bounds__(256) void k_mix_tc(
    const float* __restrict__ mb1,
    const float* __restrict__ mw2, const float* __restrict__ mb2,
    float* __restrict__ out)
{
    extern __shared__ float sm[];
    float* cs = sm;                 // 32*456 (packed cols)
    float* ms = sm + 32 * CP;       // 32*132

    const int bt0 = blockIdx.x * 32;
    const int tid = threadIdx.x;
    const int warp = tid >> 5, lane = tid & 31;
    const int grp = lane >> 2, tig = lane & 3;

    const float* cb = g_p + (size_t)bt0 * 448;
    for (int i = tid; i < 32 * 448; i += 256) {
        int r = i / 448, c = i - r * 448;
        int cp = (c & ~7) | ((c & 3) << 1) | ((c >> 2) & 1);
        cs[r * CP + cp] = cb[i];
    }
    __syncthreads();

    {
        float acc[2][2][4];
#pragma unroll
        for (int mt = 0; mt < 2; ++mt)
#pragma unroll
            for (int nt = 0; nt < 2; ++nt)
#pragma unroll
                for (int c = 0; c < 4; ++c) acc[mt][nt][c] = 0.0f;

        const float* wbase = g_wm + ((size_t)warp * 32 + lane) * 4;
        const float* c0 = cs + grp * CP + tig * 2;
#pragma unroll
        for (int kb = 0; kb < 56; ++kb) {
            const int k0 = kb * 8;
            float2 ca[2][2];
#pragma unroll
            for (int mt = 0; mt < 2; ++mt) {
                const float* cm = c0 + mt * 16 * CP + k0;
                ca[mt][0] = *(const float2*)cm;
                ca[mt][1] = *(const float2*)(cm + 8 * CP);
            }
            const float4 wv = __ldg((const float4*)(wbase + (size_t)kb * 1024));
#pragma unroll
            for (int nt = 0; nt < 2; ++nt) {
                uint32_t bf0 = __float_as_uint(nt ? wv.z : wv.x);
                uint32_t bf1 = __float_as_uint(nt ? wv.w : wv.y);
#pragma unroll
                for (int mt = 0; mt < 2; ++mt)
                    mma_tf32_p(acc[mt][nt], ca[mt][0], ca[mt][1], bf0, bf1);
            }
        }
#pragma unroll
        for (int nt = 0; nt < 2; ++nt) {
            int col0 = warp * 16 + nt * 8 + tig * 2;
            float bb0 = mb1[col0];
            float bb1 = mb1[col0 + 1];
#pragma unroll
            for (int mt = 0; mt < 2; ++mt) {
                int r0 = mt * 16 + grp;
                ms[r0 * MP + col0]           = gelu_exact(acc[mt][nt][0] + bb0);
                ms[r0 * MP + col0 + 1]       = gelu_exact(acc[mt][nt][1] + bb1);
                ms[(r0 + 8) * MP + col0]     = gelu_exact(acc[mt][nt][2] + bb0);
                ms[(r0 + 8) * MP + col0 + 1] = gelu_exact(acc[mt][nt][3] + bb1);
            }
        }
    }
    __syncthreads();

    {
        const int o = tid & 15, tb = tid >> 4;
        const float* wc = mw2 + o;
        const float bo = mb2[o];
#pragma unroll
        for (int h = 0; h < 2; ++h) {
            int tt = tb + h * 16;
            float acc = 0.0f;
#pragma unroll
            for (int e = 0; e < 128; e += 4) {
                float4 mv = *(const float4*)&ms[tt * MP + e];
                acc = fmaf(mv.x, wc[(e + 0) * 16], acc);
                acc = fmaf(mv.y, wc[(e + 1) * 16], acc);
                acc = fmaf(mv.z, wc[(e + 2) * 16], acc);
                acc = fmaf(mv.w, wc[(e + 3) * 16], acc);
            }
            out[(size_t)(bt0 + tt) * 16 + o] = acc + bo;
        }
    }
}

// ---------------------------------------------------------------------------
extern "C" void kernel_launch(void* const* d_in, const int* in_sizes, int n_in,
                              void* d_out, int out_size)
{
    const float* x      = (const float*)d_in[0];
    const float* conv_w = (const float*)d_in[1];
    const float* conv_b = (const float*)d_in[2];
    const float* dec_g  = (const float*)d_in[3];
    const float* dec_b  = (const float*)d_in[4];
    const float* n2_g   = (const float*)d_in[5];
    const float* n2_b   = (const float*)d_in[6];
    const float* ffn_w1 = (const float*)d_in[7];
    const float* ffn_b1 = (const float*)d_in[8];
    const float* ffn_w2 = (const float*)d_in[9];
    const float* ffn_b2 = (const float*)d_in[10];
    const float* proj_w = (const float*)d_in[11];
    const float* proj_b = (const float*)d_in[12];
    const float* mix_w1 = (const float*)d_in[13];
    const float* mix_b1 = (const float*)d_in[14];
    const float* mix_w2 = (const float*)d_in[15];
    const float* mix_b2 = (const float*)d_in[16];
    float* out = (float*)d_out;

    const int smem_fused = (4352 + 4224 + 4352 + 2304) * 4;   // 60928 B
    const int smem_mix   = (32 * CP + 32 * MP) * 4;           // 75264 B
    cudaFuncSetAttribute(k_fused, cudaFuncAttributeMaxDynamicSharedMemorySize, smem_fused);
    cudaFuncSetAttribute(k_mix_tc, cudaFuncAttributeMaxDynamicSharedMemorySize, smem_mix);

    k_prep<<<512, 256>>>(conv_w, ffn_w1, ffn_w2, proj_w, mix_w1);

    dim3 g1(T_ / 32, B_, NB_);
    k_fused<<<g1, 256, smem_fused>>>(x, conv_b, dec_g, dec_b, n2_g, n2_b,
                                     ffn_b1, ffn_b2, proj_b);

    dim3 g3((B_ * T_) / 32);
    k_mix_tc<<<g3, 256, smem_mix>>>(mix_b1, mix_w2, mix_b2, out);
}